// round 15
// baseline (speedup 1.0000x reference)
#include <cuda_runtime.h>
#include <cuda_fp16.h>
#include <math.h>
#include <stdint.h>

#define B 4
#define L 1024
#define D 768
#define H 12
#define NE 42
#define MM 4
#define P 512
#define BLKSZ 64
#define NL 97
#define GB 12          // D / BLKSZ
#define KSPL 2         // K-split of bilinear
#define NSL (GB*KSPL)  // 24 partial slices
#define ROWS (B*P)     // 2048
#define NENT (B*NE)    // 168

// ---------------- scratch (device globals; no allocation allowed) ----------
__device__ __align__(16) __half g_ehi[NENT*D];
__device__ __align__(16) float g_eatt[B*NE*H*L];
__device__ __align__(16) __half g_hthi[(size_t)ROWS*L];
__device__ __align__(16) __half g_rshi[(size_t)ROWS*D];
__device__ __align__(16) float g_cent[2*NENT*D];      // bias-preinit; entgemm atomically adds
__device__ __align__(16) float g_zs[(size_t)ROWS*D];
__device__ __align__(16) float g_zo[(size_t)ROWS*D];
__device__ __align__(16) float g_part[(size_t)NSL*ROWS*NL];
// fragment-ready W_bi (hi fp16): [g][kstep s:256][ntile t:13][lane:32]
__device__ __align__(16) uint2 g_Whi[(size_t)GB*256*13*32];
// fragment-ready extractor weights (hi only): [which:2][kstep:96][ntile:96][lane:32]
__device__ __align__(16) uint2 g_WxFhi[(size_t)2*96*96*32];
// fragment-ready seq (hi only): [b:4][kstep:64][ntile:96][lane:32]
__device__ __align__(16) uint2 g_seqFhi[(size_t)4*64*96*32];

// ---- half helpers ---------------------------------------------------------
__device__ __forceinline__ unsigned h2pack(float a, float b) {
    __half2 h = __float22half2_rn(make_float2(a, b));
    return reinterpret_cast<unsigned&>(h);
}
__device__ __forceinline__ unsigned hmul2u(unsigned a, unsigned b) {
    __half2 r = __hmul2(reinterpret_cast<__half2&>(a), reinterpret_cast<__half2&>(b));
    return reinterpret_cast<unsigned&>(r);
}

// ---- mma.sync m16n8k16 fp16 -> fp32 ---------------------------------------
__device__ __forceinline__ void mma16816(float* d, const unsigned* a, unsigned b0, unsigned b1) {
    asm volatile(
        "mma.sync.aligned.m16n8k16.row.col.f32.f16.f16.f32 "
        "{%0,%1,%2,%3}, {%4,%5,%6,%7}, {%8,%9}, {%0,%1,%2,%3};"
        : "+f"(d[0]), "+f"(d[1]), "+f"(d[2]), "+f"(d[3])
        : "r"(a[0]), "r"(a[1]), "r"(a[2]), "r"(a[3]), "r"(b0), "r"(b1));
}

// ---- fused kernel: entity attentions (bids 0..2015) + embeddings (2016..) -
__global__ void k_eatt_eemb(const float* __restrict__ att,
                            const float* __restrict__ seq,
                            const int* __restrict__ mpos) {
    __shared__ int pos[MM];
    const int tid = threadIdx.x;
    if ((int)blockIdx.x < B*NE*H) {
        const int idx = blockIdx.x;
        const int h  = idx % H;
        const int be = idx / H;
        const int b  = be / NE;
        if (tid < MM) pos[tid] = mpos[be*MM + tid] + 1;
        __syncthreads();
        const float* ab = att + (size_t)(b*H + h) * L * L;
        const float4* a0 = (const float4*)(ab + (size_t)pos[0]*L);
        const float4* a1 = (const float4*)(ab + (size_t)pos[1]*L);
        const float4* a2 = (const float4*)(ab + (size_t)pos[2]*L);
        const float4* a3 = (const float4*)(ab + (size_t)pos[3]*L);
        float4* o4 = (float4*)(g_eatt + ((size_t)be*H + h) * L);
        const float4 v0 = a0[tid], v1 = a1[tid], v2 = a2[tid], v3 = a3[tid];
        float4 s;
        s.x = 0.25f*(v0.x + v1.x + v2.x + v3.x);
        s.y = 0.25f*(v0.y + v1.y + v2.y + v3.y);
        s.z = 0.25f*(v0.z + v1.z + v2.z + v3.z);
        s.w = 0.25f*(v0.w + v1.w + v2.w + v3.w);
        o4[tid] = s;
    } else {
        const int be = blockIdx.x - B*NE*H;
        const int b = be / NE;
        if (tid < MM) pos[tid] = mpos[be*MM + tid] + 1;
        __syncthreads();
        if (tid < 192) {
            const float* sb = seq + (size_t)b * L * D;
            const float4 v0 = *(const float4*)(sb + (size_t)pos[0]*D + tid*4);
            const float4 v1 = *(const float4*)(sb + (size_t)pos[1]*D + tid*4);
            const float4 v2 = *(const float4*)(sb + (size_t)pos[2]*D + tid*4);
            const float4 v3 = *(const float4*)(sb + (size_t)pos[3]*D + tid*4);
            float r[4];
            #pragma unroll
            for (int j = 0; j < 4; j++) {
                const float e0 = (&v0.x)[j], e1 = (&v1.x)[j];
                const float e2 = (&v2.x)[j], e3 = (&v3.x)[j];
                float mx = fmaxf(fmaxf(e0, e1), fmaxf(e2, e3));
                float s = expf(e0-mx) + expf(e1-mx) + expf(e2-mx) + expf(e3-mx);
                r[j] = mx + logf(s);
            }
            unsigned h0 = h2pack(r[0], r[1]), h1 = h2pack(r[2], r[3]);
            *(unsigned*)&g_ehi[(size_t)be*D + tid*4]     = h0;
            *(unsigned*)&g_ehi[(size_t)be*D + tid*4 + 2] = h1;
        }
    }
}

// ---- fused: htw (0..2047) + W_bi prep (2048..5119) + cent init (5120..5371)
__global__ void k_htw_prepW(const int* __restrict__ hts, const float* __restrict__ Wbi,
                            const float* __restrict__ bh_, const float* __restrict__ bt_) {
    __shared__ float sbuf[16*97];               // prepW slab; htw uses first 256 as red
    const int tid = threadIdx.x;
    if ((int)blockIdx.x < ROWS) {
        const int bp = blockIdx.x;
        const int b  = bp / P;
        const int hi = hts[bp*2 + 0];
        const int ti = hts[bp*2 + 1];
        const float4* eh4 = (const float4*)(g_eatt + (size_t)(b*NE + hi) * H * L);
        const float4* et4 = (const float4*)(g_eatt + (size_t)(b*NE + ti) * H * L);
        float ax = 0.f, ay = 0.f, az = 0.f, aw = 0.f;
        #pragma unroll
        for (int hh = 0; hh < H; hh++) {
            const float4 a = eh4[hh*256 + tid];
            const float4 c = et4[hh*256 + tid];
            ax += a.x*c.x; ay += a.y*c.y; az += a.z*c.z; aw += a.w*c.w;
        }
        float lsum = ax + ay + az + aw;
        sbuf[tid] = lsum;
        __syncthreads();
        for (int s = 128; s > 0; s >>= 1) {
            if (tid < s) sbuf[tid] += sbuf[tid + s];
            __syncthreads();
        }
        const float total = sbuf[0];
        const float scale = 1.f / ((float)H * (total / (float)H + 1e-5f));
        *(unsigned*)&g_hthi[(size_t)bp*L + tid*4]     = h2pack(ax*scale, ay*scale);
        *(unsigned*)&g_hthi[(size_t)bp*L + tid*4 + 2] = h2pack(az*scale, aw*scale);
    } else if ((int)blockIdx.x < ROWS + 3072) {
        const int bid = blockIdx.x - ROWS;
        const int s = bid & 255, g = bid >> 8;
        const float4* src = (const float4*)(Wbi + (size_t)(g*4096 + s*16)*NL);
        for (int idx = tid; idx < 388; idx += 256)
            ((float4*)sbuf)[idx] = src[idx];
        __syncthreads();
        for (int o = tid; o < 13*32; o += 256) {
            const int t = o >> 5, lane = o & 31;
            const int n = t*8 + (lane >> 2), kk = (lane & 3)*2;
            float w00 = 0.f, w01 = 0.f, w08 = 0.f, w09 = 0.f;
            if (n < NL) {
                w00 = sbuf[(kk  )*97 + n]; w01 = sbuf[(kk+1)*97 + n];
                w08 = sbuf[(kk+8)*97 + n]; w09 = sbuf[(kk+9)*97 + n];
            }
            g_Whi[((size_t)(g*256 + s)*13 + t)*32 + lane] =
                make_uint2(h2pack(w00, w01), h2pack(w08, w09));
        }
    } else {
        const int base = ((int)blockIdx.x - (ROWS + 3072)) * 1024 + tid * 4;
        const int which = base / (NENT*D);
        const int n = base % D;
        const float* bias = which ? bt_ : bh_;
        float4 v = *(const float4*)&bias[n];
        *(float4*)&g_cent[base] = v;
    }
}

// ---- kernel: big slabs (W_head/W_tail/seq) -> fragment-ready fp16 ---------
// bids [0,192): extractor weights; [192,448): seq. dyn smem 49408 B.
__global__ void k_prepS(const float* __restrict__ Wh, const float* __restrict__ Wt,
                        const float* __restrict__ seq) {
    extern __shared__ float smf[];
    const int tid = threadIdx.x;               // 256
    const int bid = blockIdx.x;
    const float* src;
    uint2* dhi;
    if (bid < 192) {
        const int which = bid / 96, ks = bid % 96;
        src = (which ? Wt : Wh) + (size_t)ks*16*768;
        dhi = g_WxFhi + ((size_t)which*96 + ks)*96*32;
    } else {
        const int r = bid - 192;
        const int b = r / 64, ks = r % 64;
        src = seq + (size_t)b*L*D + (size_t)ks*16*768;
        dhi = g_seqFhi + ((size_t)b*64 + ks)*96*32;
    }
    for (int idx = tid; idx < 16*192; idx += 256) {
        const int kr = idx / 192, n4 = idx - kr*192;
        const float4 v = *(const float4*)(src + (size_t)kr*768 + n4*4);
        *(float4*)&smf[kr*772 + n4*4] = v;
    }
    __syncthreads();
    for (int o = tid; o < 96*32; o += 256) {
        const int nt = o >> 5, lane = o & 31;
        const int n = nt*8 + (lane >> 2), k0 = (lane & 3)*2;
        unsigned h0 = h2pack(smf[(k0  )*772 + n], smf[(k0+1)*772 + n]);
        unsigned h1 = h2pack(smf[(k0+8)*772 + n], smf[(k0+9)*772 + n]);
        dhi[(size_t)nt*32 + lane] = make_uint2(h0, h1);
    }
}

// ---- kernel: rs = htw @ seq via HMMA (1-pass fp16, 64-row blocks) ---------
// grid (12 ntile-blocks, 8 row-blocks, 4 batches) = 384, 256 threads
// dyn smem: Ah[64*72]h + Bh[1024]uint2 = 17408 B
__global__ __launch_bounds__(256) void k_rs_mma() {
    const int b  = blockIdx.z;
    const int p0 = blockIdx.y * 64;
    extern __shared__ char dsm[];
    __half* Ah = (__half*)dsm;
    uint2*  Bhs = (uint2*)(dsm + 64*72*2);
    const int tid = threadIdx.x, lane = tid & 31, wid = tid >> 5;
    const int wm = wid & 1, wn = wid >> 1;
    const size_t rowbase = (size_t)(b*P + p0);
    float acc[2][2][4] = {};
    const int rb = wm*32 + (lane >> 2);
    for (int c0 = 0; c0 < L; c0 += 64) {
        __syncthreads();
        for (int idx = tid; idx < 1024; idx += 256) {
            const int row = idx >> 4, c4 = (idx & 15)*4;
            const size_t o = (rowbase + row)*L + c0 + c4;
            *(uint2*)&Ah[row*72 + c4] = *(const uint2*)&g_hthi[o];
        }
        for (int idx = tid; idx < 1024; idx += 256) {
            const int kl = idx >> 8, rest = idx & 255;
            const int nt = blockIdx.x*8 + (rest >> 5), l2 = rest & 31;
            const size_t bi = (((size_t)b*64 + (c0 >> 4) + kl)*96 + nt)*32 + l2;
            Bhs[idx] = g_seqFhi[bi];
        }
        __syncthreads();
        #pragma unroll
        for (int kk = 0; kk < 4; kk++) {
            const int kloc = kk*16 + (lane & 3)*2;
            unsigned ah[2][4];
            #pragma unroll
            for (int m = 0; m < 2; m++) {
                const int r = rb + m*16;
                ah[m][0] = *(const unsigned*)&Ah[ r   *72 + kloc];
                ah[m][1] = *(const unsigned*)&Ah[(r+8)*72 + kloc];
                ah[m][2] = *(const unsigned*)&Ah[ r   *72 + kloc + 8];
                ah[m][3] = *(const unsigned*)&Ah[(r+8)*72 + kloc + 8];
            }
            #pragma unroll
            for (int t = 0; t < 2; t++) {
                const int bi = (kk*8 + wn*2 + t)*32 + lane;
                const uint2 bh = Bhs[bi];
                #pragma unroll
                for (int m = 0; m < 2; m++)
                    mma16816(acc[m][t], ah[m], bh.x, bh.y);
            }
        }
    }
    #pragma unroll
    for (int m = 0; m < 2; m++) {
        const size_t r = rowbase + wm*32 + m*16 + (lane >> 2);
        #pragma unroll
        for (int t = 0; t < 2; t++) {
            const int n = blockIdx.x*64 + wn*16 + t*8 + (lane & 3)*2;
            *(unsigned*)&g_rshi[ r   *D + n] = h2pack(acc[m][t][0], acc[m][t][1]);
            *(unsigned*)&g_rshi[(r+8)*D + n] = h2pack(acc[m][t][2], acc[m][t][3]);
        }
    }
}

// ---- kernel: entity-side extractor GEMM, SPLIT-K, 1-pass fp16 -------------
// grid (24 ntile, 2 rowblocks, 8 = which*4+ks), 256 threads
#define EG_STR 200
// dyn smem: Ah 128*200*2 + Bhs 1536*8 = 63488 B
__global__ __launch_bounds__(256) void k_entgemm(int dummy) {
    const int which = blockIdx.z >> 2;
    const int ks    = blockIdx.z & 3;
    const int r0 = blockIdx.y * 128;
    const int c0 = ks * 192;
    extern __shared__ char dsm[];
    __half* Ah = (__half*)dsm;
    uint2*  Bhs = (uint2*)(dsm + 128*EG_STR*2);
    const int tid = threadIdx.x, lane = tid & 31, wid = tid >> 5;
    const int wm = wid & 3, wn = wid >> 2;
    const uint2* __restrict__ WFh = g_WxFhi + (size_t)which*96*96*32;
    float acc[2][2][4] = {};
    const int rb = wm*32 + (lane >> 2);
    for (int idx = tid; idx < 6144; idx += 256) {
        const int row = idx / 48, c4 = (idx - row*48)*4;
        int be = r0 + row; if (be >= NENT) be = 0;
        const size_t o = (size_t)be*D + c0 + c4;
        *(uint2*)&Ah[row*EG_STR + c4] = *(const uint2*)&g_ehi[o];
    }
    for (int idx = tid; idx < 1536; idx += 256) {
        const int kl = idx >> 7, rest = idx & 127;
        const int nt = blockIdx.x*4 + (rest >> 5), l2 = rest & 31;
        Bhs[idx] = WFh[((size_t)((c0 >> 4) + kl)*96 + nt)*32 + l2];
    }
    __syncthreads();
    #pragma unroll
    for (int kk = 0; kk < 12; kk++) {
        const int kloc = kk*16 + (lane & 3)*2;
        unsigned ah[2][4];
        #pragma unroll
        for (int m = 0; m < 2; m++) {
            const int r = rb + m*16;
            ah[m][0] = *(const unsigned*)&Ah[ r   *EG_STR + kloc];
            ah[m][1] = *(const unsigned*)&Ah[(r+8)*EG_STR + kloc];
            ah[m][2] = *(const unsigned*)&Ah[ r   *EG_STR + kloc + 8];
            ah[m][3] = *(const unsigned*)&Ah[(r+8)*EG_STR + kloc + 8];
        }
        #pragma unroll
        for (int t = 0; t < 2; t++) {
            const int bi = (kk*4 + wn*2 + t)*32 + lane;
            const uint2 bh = Bhs[bi];
            #pragma unroll
            for (int m = 0; m < 2; m++)
                mma16816(acc[m][t], ah[m], bh.x, bh.y);
        }
    }
    float* cent = g_cent + (size_t)which*NENT*D;
    #pragma unroll
    for (int m = 0; m < 2; m++) {
        const int r = r0 + wm*32 + m*16 + (lane >> 2);
        #pragma unroll
        for (int t = 0; t < 2; t++) {
            const int n = blockIdx.x*32 + wn*16 + t*8 + (lane & 3)*2;
            if (r < NENT) {
                atomicAdd(&cent[(size_t)r*D + n  ], acc[m][t][0]);
                atomicAdd(&cent[(size_t)r*D + n+1], acc[m][t][1]);
            }
            if (r + 8 < NENT) {
                atomicAdd(&cent[(size_t)(r+8)*D + n  ], acc[m][t][2]);
                atomicAdd(&cent[(size_t)(r+8)*D + n+1], acc[m][t][3]);
            }
        }
    }
}

// ---- kernel: pair extractor: z = tanh(rs @ W2 + cent[ent(p)]) -------------
// 1-pass fp16; grid.x = 24 (which*12+nb), grid.y = 16; 256 threads
__global__ __launch_bounds__(256) void k_extract2(const int* __restrict__ hts) {
    const int which = blockIdx.x / 12;
    const int nb    = blockIdx.x % 12;
    const int r0 = blockIdx.y * 128;
    extern __shared__ char dsm[];
    __half* Ah = (__half*)dsm;
    uint2*  Bhs = (uint2*)(dsm + 128*72*2);
    int*    eoff = (int*)(Bhs + 1024);
    const int tid = threadIdx.x, lane = tid & 31, wid = tid >> 5;
    const int wm = wid & 3, wn = wid >> 2;
    if (tid < 128) {
        const int row = r0 + tid;
        eoff[tid] = ((row / P)*NE + hts[row*2 + which]) * D;
    }
    const uint2* __restrict__ WFh = g_WxFhi + (size_t)which*96*96*32;
    float acc[2][4][4] = {};
    const int rb = wm*32 + (lane >> 2);
    for (int c0 = 0; c0 < D; c0 += 64) {
        __syncthreads();
        for (int idx = tid; idx < 2048; idx += 256) {
            const int row = idx >> 4, c4 = (idx & 15)*4;
            const size_t o = (size_t)(r0 + row)*D + c0 + c4;
            *(uint2*)&Ah[row*72 + c4] = *(const uint2*)&g_rshi[o];
        }
        for (int idx = tid; idx < 1024; idx += 256) {
            const int kl = idx >> 8, rest = idx & 255;
            const int nt = nb*8 + (rest >> 5), l2 = rest & 31;
            Bhs[idx] = WFh[((size_t)(48 + (c0 >> 4) + kl)*96 + nt)*32 + l2];
        }
        __syncthreads();
        #pragma unroll
        for (int kk = 0; kk < 4; kk++) {
            const int kloc = kk*16 + (lane & 3)*2;
            unsigned ah[2][4];
            #pragma unroll
            for (int m = 0; m < 2; m++) {
                const int r = rb + m*16;
                ah[m][0] = *(const unsigned*)&Ah[ r   *72 + kloc];
                ah[m][1] = *(const unsigned*)&Ah[(r+8)*72 + kloc];
                ah[m][2] = *(const unsigned*)&Ah[ r   *72 + kloc + 8];
                ah[m][3] = *(const unsigned*)&Ah[(r+8)*72 + kloc + 8];
            }
            #pragma unroll
            for (int t = 0; t < 4; t++) {
                const int bi = (kk*8 + wn*4 + t)*32 + lane;
                const uint2 bh = Bhs[bi];
                #pragma unroll
                for (int m = 0; m < 2; m++)
                    mma16816(acc[m][t], ah[m], bh.x, bh.y);
            }
        }
    }
    float* outb = which ? g_zo : g_zs;
    const float* cent = g_cent + (size_t)which*NENT*D;
    #pragma unroll
    for (int m = 0; m < 2; m++) {
        const int lr = wm*32 + m*16 + (lane >> 2);
        const int r = r0 + lr;
        #pragma unroll
        for (int t = 0; t < 4; t++) {
            const int n = nb*64 + wn*32 + t*8 + (lane & 3)*2;
            const float* c0p = cent + eoff[lr];
            const float* c1p = cent + eoff[lr + 8];
            outb[(size_t) r   *D + n  ] = tanhf(acc[m][t][0] + c0p[n]);
            outb[(size_t) r   *D + n+1] = tanhf(acc[m][t][1] + c0p[n+1]);
            outb[(size_t)(r+8)*D + n  ] = tanhf(acc[m][t][2] + c1p[n]);
            outb[(size_t)(r+8)*D + n+1] = tanhf(acc[m][t][3] + c1p[n+1]);
        }
    }
}

// ---- kernel: bilinear logits via HMMA; 128 threads, 4 warps x 2 M-tiles ---
// grid (16 rowblocks, 12 g, KSPL halves)
#define ZSH 40   // half stride for zs slice
#define ZOP 34   // uint (half2) stride for zo pairs
// dyn smem: zs 128*40*2=10240 + zo 128*34*4=17408 + Wst 8*13*32*8=26624 = 54272
__global__ __launch_bounds__(128) void k_blmma() {
    const int g    = blockIdx.y;
    const int r0   = blockIdx.x * 128;
    const int half = blockIdx.z;
    extern __shared__ char shb[];
    __half*   zs_h = (__half*)shb;
    unsigned* zo_p = (unsigned*)(shb + 128*ZSH*2);
    uint2*    Wst  = (uint2*)(shb + 128*ZSH*2 + 128*ZOP*4);
    const int tid = threadIdx.x, lane = tid & 31, wid = tid >> 5;

    for (int idx = tid; idx < 128*8; idx += 128) {
        const int row = idx >> 3, c4 = (idx & 7) * 4;
        float4 a = *(const float4*)&g_zs[(size_t)(r0+row)*D + g*BLKSZ + half*32 + c4];
        *(unsigned*)&zs_h[row*ZSH + c4]     = h2pack(a.x, a.y);
        *(unsigned*)&zs_h[row*ZSH + c4 + 2] = h2pack(a.z, a.w);
    }
    for (int idx = tid; idx < 128*16; idx += 128) {
        const int row = idx >> 4, c4 = (idx & 15) * 4;
        float4 b = *(const float4*)&g_zo[(size_t)(r0+row)*D + g*BLKSZ + c4];
        zo_p[row*ZOP + (idx & 15)*2]     = h2pack(b.x, b.y);
        zo_p[row*ZOP + (idx & 15)*2 + 1] = h2pack(b.z, b.w);
    }

    float acc[2][13][4] = {};
    const int rl = wid*32 + (lane >> 2);       // m-tiles: rows rl/rl+8 and rl+16/rl+24
    const int jpo = lane & 3;
    const uint2* __restrict__ Wh = g_Whi + ((size_t)g*256 + half*128)*13*32;

    for (int sc = 0; sc < 128; sc += 8) {
        __syncthreads();
        for (int idx = tid; idx < 8*13*32; idx += 128)
            Wst[idx] = Wh[(size_t)sc*13*32 + idx];
        __syncthreads();
        #pragma unroll
        for (int sl = 0; sl < 8; sl++) {
            const int s = sc + sl;
            const int i  = s >> 2;
            const int jp = ((s & 3) << 3) + jpo;
            unsigned ah[2][4];
            #pragma unroll
            for (int m = 0; m < 2; m++) {
                const int r = rl + m*16;
                const __half2 z0 = __half2half2(zs_h[ r   *ZSH + i]);
                const __half2 z1 = __half2half2(zs_h[(r+8)*ZSH + i]);
                const unsigned zs0 = reinterpret_cast<const unsigned&>(z0);
                const unsigned zs1 = reinterpret_cast<const unsigned&>(z1);
                ah[m][0] = hmul2u(zs0, zo_p[ r   *ZOP + jp]);
                ah[m][1] = hmul2u(zs1, zo_p[(r+8)*ZOP + jp]);
                ah[m][2] = hmul2u(zs0, zo_p[ r   *ZOP + jp + 4]);
                ah[m][3] = hmul2u(zs1, zo_p[(r+8)*ZOP + jp + 4]);
            }
            #pragma unroll
            for (int t = 0; t < 13; t++) {
                const uint2 bh = Wst[(sl*13 + t)*32 + lane];
                mma16816(acc[0][t], ah[0], bh.x, bh.y);
                mma16816(acc[1][t], ah[1], bh.x, bh.y);
            }
        }
    }

    float* outp = g_part + ((size_t)(g*KSPL + half) * ROWS + r0) * NL;
    #pragma unroll
    for (int m = 0; m < 2; m++) {
        const int r = rl + m*16;
        #pragma unroll
        for (int t = 0; t < 13; t++) {
            const int n = t*8 + (lane & 3)*2;
            if (n < NL) {
                outp[(size_t) r   *NL + n] = acc[m][t][0];
                outp[(size_t)(r+8)*NL + n] = acc[m][t][2];
            }
            if (n + 1 < NL) {
                outp[(size_t) r   *NL + n+1] = acc[m][t][1];
                outp[(size_t)(r+8)*NL + n+1] = acc[m][t][3];
            }
        }
    }
}

// ---- kernel: reduce partials over slices, add bias ------------------------
__global__ void k_reduce(const float* __restrict__ b_bi, float* __restrict__ out) {
    const int idx = blockIdx.x * 256 + threadIdx.x;
    if (idx >= ROWS * NL) return;
    const int n = idx % NL;
    float s = b_bi[n];
    #pragma unroll
    for (int g = 0; g < NSL; g++)
        s += g_part[(size_t)g * (ROWS*NL) + idx];
    out[idx] = s;
}

// ---------------------------------------------------------------------------
extern "C" void kernel_launch(void* const* d_in, const int* in_sizes, int n_in,
                              void* d_out, int out_size) {
    const float* seq    = (const float*)d_in[0];
    const float* att    = (const float*)d_in[1];
    const int*   mpos   = (const int*)d_in[2];
    const int*   hts    = (const int*)d_in[3];
    const float* W_head = (const float*)d_in[4];
    const float* b_head = (const float*)d_in[5];
    const float* W_tail = (const float*)d_in[6];
    const float* b_tail = (const float*)d_in[7];
    const float* W_bi   = (const float*)d_in[8];
    const float* b_bi   = (const float*)d_in[9];
    float* out = (float*)d_out;

    const int blm_smem = 128*ZSH*2 + 128*ZOP*4 + 8*13*32*8;        // 54272
    const int ps_smem  = 16*772*4;                                  // 49408
    const int rs_smem  = 64*72*2 + 1024*8;                          // 17408
    const int eg_smem  = 128*EG_STR*2 + 1536*8;                     // 63488
    const int ex_smem  = 128*72*2 + 1024*8 + 512;                   // 27136
    cudaFuncSetAttribute(k_blmma, cudaFuncAttributeMaxDynamicSharedMemorySize, blm_smem);
    cudaFuncSetAttribute(k_prepS, cudaFuncAttributeMaxDynamicSharedMemorySize, ps_smem);
    cudaFuncSetAttribute(k_rs_mma, cudaFuncAttributeMaxDynamicSharedMemorySize, rs_smem);
    cudaFuncSetAttribute(k_entgemm, cudaFuncAttributeMaxDynamicSharedMemorySize, eg_smem);
    cudaFuncSetAttribute(k_extract2, cudaFuncAttributeMaxDynamicSharedMemorySize, ex_smem);

    k_eatt_eemb<<<B*NE*H + B*NE, 256>>>(att, seq, mpos);
    k_prepS<<<448, 256, ps_smem>>>(W_head, W_tail, seq);
    k_htw_prepW<<<ROWS + 3072 + 252, 256>>>(hts, W_bi, b_head, b_tail);
    dim3 geg(24, 2, 8);
    k_entgemm<<<geg, 256, eg_smem>>>(0);
    dim3 grs(D/64, P/64, B);
    k_rs_mma<<<grs, 256, rs_smem>>>();
    dim3 gex(24, ROWS/128);
    k_extract2<<<gex, 256, ex_smem>>>(hts);
    dim3 glg(ROWS/128, GB, KSPL);
    k_blmma<<<glg, 128, blm_smem>>>();
    k_reduce<<<(ROWS*NL + 255)/256, 256>>>(b_bi, out);
}

// round 16
// speedup vs baseline: 1.0993x; 1.0993x over previous
#include <cuda_runtime.h>
#include <cuda_fp16.h>
#include <math.h>
#include <stdint.h>

#define B 4
#define L 1024
#define D 768
#define H 12
#define NE 42
#define MM 4
#define P 512
#define BLKSZ 64
#define NL 97
#define GB 12          // D / BLKSZ
#define KSPL 2         // K-split of bilinear
#define NSL (GB*KSPL)  // 24 partial slices
#define ROWS (B*P)     // 2048
#define NENT (B*NE)    // 168

// ---------------- scratch (device globals; no allocation allowed) ----------
__device__ __align__(16) __half g_ehi[NENT*D];
__device__ __align__(16) float g_eatt[B*NE*H*L];
__device__ __align__(16) __half g_hthi[(size_t)ROWS*L];
__device__ __align__(16) __half g_rshi[(size_t)ROWS*D];
__device__ __align__(16) float g_cent[2*NENT*D];      // bias-preinit; entgemm atomically adds
__device__ __align__(16) float g_zs[(size_t)ROWS*D];
__device__ __align__(16) float g_zo[(size_t)ROWS*D];
__device__ __align__(16) float g_part[(size_t)NSL*ROWS*NL];
// fragment-ready W_bi (hi fp16): [g][kstep s:256][ntile t:13][lane:32]
__device__ __align__(16) uint2 g_Whi[(size_t)GB*256*13*32];
// fragment-ready extractor weights (hi only): [which:2][kstep:96][ntile:96][lane:32]
__device__ __align__(16) uint2 g_WxFhi[(size_t)2*96*96*32];
// fragment-ready seq (hi only): [b:4][kstep:64][ntile:96][lane:32]
__device__ __align__(16) uint2 g_seqFhi[(size_t)4*64*96*32];

// ---- half helpers ---------------------------------------------------------
__device__ __forceinline__ unsigned h2pack(float a, float b) {
    __half2 h = __float22half2_rn(make_float2(a, b));
    return reinterpret_cast<unsigned&>(h);
}
__device__ __forceinline__ unsigned hmul2u(unsigned a, unsigned b) {
    __half2 r = __hmul2(reinterpret_cast<__half2&>(a), reinterpret_cast<__half2&>(b));
    return reinterpret_cast<unsigned&>(r);
}

// ---- mma.sync m16n8k16 fp16 -> fp32 ---------------------------------------
__device__ __forceinline__ void mma16816(float* d, const unsigned* a, unsigned b0, unsigned b1) {
    asm volatile(
        "mma.sync.aligned.m16n8k16.row.col.f32.f16.f16.f32 "
        "{%0,%1,%2,%3}, {%4,%5,%6,%7}, {%8,%9}, {%0,%1,%2,%3};"
        : "+f"(d[0]), "+f"(d[1]), "+f"(d[2]), "+f"(d[3])
        : "r"(a[0]), "r"(a[1]), "r"(a[2]), "r"(a[3]), "r"(b0), "r"(b1));
}

// ---- fused kernel: entity attentions (bids 0..2015) + embeddings (2016..) -
__global__ void k_eatt_eemb(const float* __restrict__ att,
                            const float* __restrict__ seq,
                            const int* __restrict__ mpos) {
    __shared__ int pos[MM];
    const int tid = threadIdx.x;
    if ((int)blockIdx.x < B*NE*H) {
        const int idx = blockIdx.x;
        const int h  = idx % H;
        const int be = idx / H;
        const int b  = be / NE;
        if (tid < MM) pos[tid] = mpos[be*MM + tid] + 1;
        __syncthreads();
        const float* ab = att + (size_t)(b*H + h) * L * L;
        const float4* a0 = (const float4*)(ab + (size_t)pos[0]*L);
        const float4* a1 = (const float4*)(ab + (size_t)pos[1]*L);
        const float4* a2 = (const float4*)(ab + (size_t)pos[2]*L);
        const float4* a3 = (const float4*)(ab + (size_t)pos[3]*L);
        float4* o4 = (float4*)(g_eatt + ((size_t)be*H + h) * L);
        const float4 v0 = a0[tid], v1 = a1[tid], v2 = a2[tid], v3 = a3[tid];
        float4 s;
        s.x = 0.25f*(v0.x + v1.x + v2.x + v3.x);
        s.y = 0.25f*(v0.y + v1.y + v2.y + v3.y);
        s.z = 0.25f*(v0.z + v1.z + v2.z + v3.z);
        s.w = 0.25f*(v0.w + v1.w + v2.w + v3.w);
        o4[tid] = s;
    } else {
        const int be = blockIdx.x - B*NE*H;
        const int b = be / NE;
        if (tid < MM) pos[tid] = mpos[be*MM + tid] + 1;
        __syncthreads();
        if (tid < 192) {
            const float* sb = seq + (size_t)b * L * D;
            const float4 v0 = *(const float4*)(sb + (size_t)pos[0]*D + tid*4);
            const float4 v1 = *(const float4*)(sb + (size_t)pos[1]*D + tid*4);
            const float4 v2 = *(const float4*)(sb + (size_t)pos[2]*D + tid*4);
            const float4 v3 = *(const float4*)(sb + (size_t)pos[3]*D + tid*4);
            float r[4];
            #pragma unroll
            for (int j = 0; j < 4; j++) {
                const float e0 = (&v0.x)[j], e1 = (&v1.x)[j];
                const float e2 = (&v2.x)[j], e3 = (&v3.x)[j];
                float mx = fmaxf(fmaxf(e0, e1), fmaxf(e2, e3));
                float s = expf(e0-mx) + expf(e1-mx) + expf(e2-mx) + expf(e3-mx);
                r[j] = mx + logf(s);
            }
            unsigned h0 = h2pack(r[0], r[1]), h1 = h2pack(r[2], r[3]);
            *(unsigned*)&g_ehi[(size_t)be*D + tid*4]     = h0;
            *(unsigned*)&g_ehi[(size_t)be*D + tid*4 + 2] = h1;
        }
    }
}

// ---- fused: htw (0..2047) + W_bi prep (2048..5119) + cent init (5120..5371)
__global__ void k_htw_prepW(const int* __restrict__ hts, const float* __restrict__ Wbi,
                            const float* __restrict__ bh_, const float* __restrict__ bt_) {
    __shared__ float sbuf[16*97];               // prepW slab; htw uses first 256 as red
    const int tid = threadIdx.x;
    if ((int)blockIdx.x < ROWS) {
        const int bp = blockIdx.x;
        const int b  = bp / P;
        const int hi = hts[bp*2 + 0];
        const int ti = hts[bp*2 + 1];
        const float4* eh4 = (const float4*)(g_eatt + (size_t)(b*NE + hi) * H * L);
        const float4* et4 = (const float4*)(g_eatt + (size_t)(b*NE + ti) * H * L);
        float ax = 0.f, ay = 0.f, az = 0.f, aw = 0.f;
        #pragma unroll
        for (int hh = 0; hh < H; hh++) {
            const float4 a = eh4[hh*256 + tid];
            const float4 c = et4[hh*256 + tid];
            ax += a.x*c.x; ay += a.y*c.y; az += a.z*c.z; aw += a.w*c.w;
        }
        float lsum = ax + ay + az + aw;
        sbuf[tid] = lsum;
        __syncthreads();
        for (int s = 128; s > 0; s >>= 1) {
            if (tid < s) sbuf[tid] += sbuf[tid + s];
            __syncthreads();
        }
        const float total = sbuf[0];
        const float scale = 1.f / ((float)H * (total / (float)H + 1e-5f));
        *(unsigned*)&g_hthi[(size_t)bp*L + tid*4]     = h2pack(ax*scale, ay*scale);
        *(unsigned*)&g_hthi[(size_t)bp*L + tid*4 + 2] = h2pack(az*scale, aw*scale);
    } else if ((int)blockIdx.x < ROWS + 3072) {
        const int bid = blockIdx.x - ROWS;
        const int s = bid & 255, g = bid >> 8;
        const float4* src = (const float4*)(Wbi + (size_t)(g*4096 + s*16)*NL);
        for (int idx = tid; idx < 388; idx += 256)
            ((float4*)sbuf)[idx] = src[idx];
        __syncthreads();
        for (int o = tid; o < 13*32; o += 256) {
            const int t = o >> 5, lane = o & 31;
            const int n = t*8 + (lane >> 2), kk = (lane & 3)*2;
            float w00 = 0.f, w01 = 0.f, w08 = 0.f, w09 = 0.f;
            if (n < NL) {
                w00 = sbuf[(kk  )*97 + n]; w01 = sbuf[(kk+1)*97 + n];
                w08 = sbuf[(kk+8)*97 + n]; w09 = sbuf[(kk+9)*97 + n];
            }
            g_Whi[((size_t)(g*256 + s)*13 + t)*32 + lane] =
                make_uint2(h2pack(w00, w01), h2pack(w08, w09));
        }
    } else {
        const int base = ((int)blockIdx.x - (ROWS + 3072)) * 1024 + tid * 4;
        const int which = base / (NENT*D);
        const int n = base % D;
        const float* bias = which ? bt_ : bh_;
        float4 v = *(const float4*)&bias[n];
        *(float4*)&g_cent[base] = v;
    }
}

// ---- kernel: big slabs (W_head/W_tail/seq) -> fragment-ready fp16 ---------
// bids [0,192): extractor weights; [192,448): seq. dyn smem 49408 B.
__global__ void k_prepS(const float* __restrict__ Wh, const float* __restrict__ Wt,
                        const float* __restrict__ seq) {
    extern __shared__ float smf[];
    const int tid = threadIdx.x;               // 256
    const int bid = blockIdx.x;
    const float* src;
    uint2* dhi;
    if (bid < 192) {
        const int which = bid / 96, ks = bid % 96;
        src = (which ? Wt : Wh) + (size_t)ks*16*768;
        dhi = g_WxFhi + ((size_t)which*96 + ks)*96*32;
    } else {
        const int r = bid - 192;
        const int b = r / 64, ks = r % 64;
        src = seq + (size_t)b*L*D + (size_t)ks*16*768;
        dhi = g_seqFhi + ((size_t)b*64 + ks)*96*32;
    }
    for (int idx = tid; idx < 16*192; idx += 256) {
        const int kr = idx / 192, n4 = idx - kr*192;
        const float4 v = *(const float4*)(src + (size_t)kr*768 + n4*4);
        *(float4*)&smf[kr*772 + n4*4] = v;
    }
    __syncthreads();
    for (int o = tid; o < 96*32; o += 256) {
        const int nt = o >> 5, lane = o & 31;
        const int n = nt*8 + (lane >> 2), k0 = (lane & 3)*2;
        unsigned h0 = h2pack(smf[(k0  )*772 + n], smf[(k0+1)*772 + n]);
        unsigned h1 = h2pack(smf[(k0+8)*772 + n], smf[(k0+9)*772 + n]);
        dhi[(size_t)nt*32 + lane] = make_uint2(h0, h1);
    }
}

// ---- kernel: rs = htw @ seq via HMMA (1-pass fp16, 64-row blocks) ---------
// grid (12 ntile-blocks, 8 row-blocks, 4 batches) = 384, 256 threads
// dyn smem: Ah[64*72]h + Bh[1024]uint2 = 17408 B
__global__ __launch_bounds__(256) void k_rs_mma() {
    const int b  = blockIdx.z;
    const int p0 = blockIdx.y * 64;
    extern __shared__ char dsm[];
    __half* Ah = (__half*)dsm;
    uint2*  Bhs = (uint2*)(dsm + 64*72*2);
    const int tid = threadIdx.x, lane = tid & 31, wid = tid >> 5;
    const int wm = wid & 1, wn = wid >> 1;
    const size_t rowbase = (size_t)(b*P + p0);
    float acc[2][2][4] = {};
    const int rb = wm*32 + (lane >> 2);
    for (int c0 = 0; c0 < L; c0 += 64) {
        __syncthreads();
        for (int idx = tid; idx < 1024; idx += 256) {
            const int row = idx >> 4, c4 = (idx & 15)*4;
            const size_t o = (rowbase + row)*L + c0 + c4;
            *(uint2*)&Ah[row*72 + c4] = *(const uint2*)&g_hthi[o];
        }
        for (int idx = tid; idx < 1024; idx += 256) {
            const int kl = idx >> 8, rest = idx & 255;
            const int nt = blockIdx.x*8 + (rest >> 5), l2 = rest & 31;
            const size_t bi = (((size_t)b*64 + (c0 >> 4) + kl)*96 + nt)*32 + l2;
            Bhs[idx] = g_seqFhi[bi];
        }
        __syncthreads();
        #pragma unroll
        for (int kk = 0; kk < 4; kk++) {
            const int kloc = kk*16 + (lane & 3)*2;
            unsigned ah[2][4];
            #pragma unroll
            for (int m = 0; m < 2; m++) {
                const int r = rb + m*16;
                ah[m][0] = *(const unsigned*)&Ah[ r   *72 + kloc];
                ah[m][1] = *(const unsigned*)&Ah[(r+8)*72 + kloc];
                ah[m][2] = *(const unsigned*)&Ah[ r   *72 + kloc + 8];
                ah[m][3] = *(const unsigned*)&Ah[(r+8)*72 + kloc + 8];
            }
            #pragma unroll
            for (int t = 0; t < 2; t++) {
                const int bi = (kk*8 + wn*2 + t)*32 + lane;
                const uint2 bh = Bhs[bi];
                #pragma unroll
                for (int m = 0; m < 2; m++)
                    mma16816(acc[m][t], ah[m], bh.x, bh.y);
            }
        }
    }
    #pragma unroll
    for (int m = 0; m < 2; m++) {
        const size_t r = rowbase + wm*32 + m*16 + (lane >> 2);
        #pragma unroll
        for (int t = 0; t < 2; t++) {
            const int n = blockIdx.x*64 + wn*16 + t*8 + (lane & 3)*2;
            *(unsigned*)&g_rshi[ r   *D + n] = h2pack(acc[m][t][0], acc[m][t][1]);
            *(unsigned*)&g_rshi[(r+8)*D + n] = h2pack(acc[m][t][2], acc[m][t][3]);
        }
    }
}

// ---- kernel: entity-side extractor GEMM, SPLIT-K, 1-pass fp16 -------------
// grid (24 ntile, 2 rowblocks, 8 = which*4+ks), 256 threads
#define EG_STR 200
// dyn smem: Ah 128*200*2 + Bhs 1536*8 = 63488 B
__global__ __launch_bounds__(256) void k_entgemm(int dummy) {
    const int which = blockIdx.z >> 2;
    const int ks    = blockIdx.z & 3;
    const int r0 = blockIdx.y * 128;
    const int c0 = ks * 192;
    extern __shared__ char dsm[];
    __half* Ah = (__half*)dsm;
    uint2*  Bhs = (uint2*)(dsm + 128*EG_STR*2);
    const int tid = threadIdx.x, lane = tid & 31, wid = tid >> 5;
    const int wm = wid & 3, wn = wid >> 2;
    const uint2* __restrict__ WFh = g_WxFhi + (size_t)which*96*96*32;
    float acc[2][2][4] = {};
    const int rb = wm*32 + (lane >> 2);
    for (int idx = tid; idx < 6144; idx += 256) {
        const int row = idx / 48, c4 = (idx - row*48)*4;
        int be = r0 + row; if (be >= NENT) be = 0;
        const size_t o = (size_t)be*D + c0 + c4;
        *(uint2*)&Ah[row*EG_STR + c4] = *(const uint2*)&g_ehi[o];
    }
    for (int idx = tid; idx < 1536; idx += 256) {
        const int kl = idx >> 7, rest = idx & 127;
        const int nt = blockIdx.x*4 + (rest >> 5), l2 = rest & 31;
        Bhs[idx] = WFh[((size_t)((c0 >> 4) + kl)*96 + nt)*32 + l2];
    }
    __syncthreads();
    #pragma unroll
    for (int kk = 0; kk < 12; kk++) {
        const int kloc = kk*16 + (lane & 3)*2;
        unsigned ah[2][4];
        #pragma unroll
        for (int m = 0; m < 2; m++) {
            const int r = rb + m*16;
            ah[m][0] = *(const unsigned*)&Ah[ r   *EG_STR + kloc];
            ah[m][1] = *(const unsigned*)&Ah[(r+8)*EG_STR + kloc];
            ah[m][2] = *(const unsigned*)&Ah[ r   *EG_STR + kloc + 8];
            ah[m][3] = *(const unsigned*)&Ah[(r+8)*EG_STR + kloc + 8];
        }
        #pragma unroll
        for (int t = 0; t < 2; t++) {
            const int bi = (kk*4 + wn*2 + t)*32 + lane;
            const uint2 bh = Bhs[bi];
            #pragma unroll
            for (int m = 0; m < 2; m++)
                mma16816(acc[m][t], ah[m], bh.x, bh.y);
        }
    }
    float* cent = g_cent + (size_t)which*NENT*D;
    #pragma unroll
    for (int m = 0; m < 2; m++) {
        const int r = r0 + wm*32 + m*16 + (lane >> 2);
        #pragma unroll
        for (int t = 0; t < 2; t++) {
            const int n = blockIdx.x*32 + wn*16 + t*8 + (lane & 3)*2;
            if (r < NENT) {
                atomicAdd(&cent[(size_t)r*D + n  ], acc[m][t][0]);
                atomicAdd(&cent[(size_t)r*D + n+1], acc[m][t][1]);
            }
            if (r + 8 < NENT) {
                atomicAdd(&cent[(size_t)(r+8)*D + n  ], acc[m][t][2]);
                atomicAdd(&cent[(size_t)(r+8)*D + n+1], acc[m][t][3]);
            }
        }
    }
}

// ---- kernel: pair extractor: z = tanh(rs @ W2 + cent[ent(p)]) -------------
// 1-pass fp16; grid.x = 24 (which*12+nb), grid.y = 16; 256 threads
__global__ __launch_bounds__(256) void k_extract2(const int* __restrict__ hts) {
    const int which = blockIdx.x / 12;
    const int nb    = blockIdx.x % 12;
    const int r0 = blockIdx.y * 128;
    extern __shared__ char dsm[];
    __half* Ah = (__half*)dsm;
    uint2*  Bhs = (uint2*)(dsm + 128*72*2);
    int*    eoff = (int*)(Bhs + 1024);
    const int tid = threadIdx.x, lane = tid & 31, wid = tid >> 5;
    const int wm = wid & 3, wn = wid >> 2;
    if (tid < 128) {
        const int row = r0 + tid;
        eoff[tid] = ((row / P)*NE + hts[row*2 + which]) * D;
    }
    const uint2* __restrict__ WFh = g_WxFhi + (size_t)which*96*96*32;
    float acc[2][4][4] = {};
    const int rb = wm*32 + (lane >> 2);
    for (int c0 = 0; c0 < D; c0 += 64) {
        __syncthreads();
        for (int idx = tid; idx < 2048; idx += 256) {
            const int row = idx >> 4, c4 = (idx & 15)*4;
            const size_t o = (size_t)(r0 + row)*D + c0 + c4;
            *(uint2*)&Ah[row*72 + c4] = *(const uint2*)&g_rshi[o];
        }
        for (int idx = tid; idx < 1024; idx += 256) {
            const int kl = idx >> 8, rest = idx & 255;
            const int nt = nb*8 + (rest >> 5), l2 = rest & 31;
            Bhs[idx] = WFh[((size_t)(48 + (c0 >> 4) + kl)*96 + nt)*32 + l2];
        }
        __syncthreads();
        #pragma unroll
        for (int kk = 0; kk < 4; kk++) {
            const int kloc = kk*16 + (lane & 3)*2;
            unsigned ah[2][4];
            #pragma unroll
            for (int m = 0; m < 2; m++) {
                const int r = rb + m*16;
                ah[m][0] = *(const unsigned*)&Ah[ r   *72 + kloc];
                ah[m][1] = *(const unsigned*)&Ah[(r+8)*72 + kloc];
                ah[m][2] = *(const unsigned*)&Ah[ r   *72 + kloc + 8];
                ah[m][3] = *(const unsigned*)&Ah[(r+8)*72 + kloc + 8];
            }
            #pragma unroll
            for (int t = 0; t < 4; t++) {
                const int bi = (kk*8 + wn*4 + t)*32 + lane;
                const uint2 bh = Bhs[bi];
                #pragma unroll
                for (int m = 0; m < 2; m++)
                    mma16816(acc[m][t], ah[m], bh.x, bh.y);
            }
        }
    }
    float* outb = which ? g_zo : g_zs;
    const float* cent = g_cent + (size_t)which*NENT*D;
    #pragma unroll
    for (int m = 0; m < 2; m++) {
        const int lr = wm*32 + m*16 + (lane >> 2);
        const int r = r0 + lr;
        #pragma unroll
        for (int t = 0; t < 4; t++) {
            const int n = nb*64 + wn*32 + t*8 + (lane & 3)*2;
            const float* c0p = cent + eoff[lr];
            const float* c1p = cent + eoff[lr + 8];
            outb[(size_t) r   *D + n  ] = tanhf(acc[m][t][0] + c0p[n]);
            outb[(size_t) r   *D + n+1] = tanhf(acc[m][t][1] + c0p[n+1]);
            outb[(size_t)(r+8)*D + n  ] = tanhf(acc[m][t][2] + c1p[n]);
            outb[(size_t)(r+8)*D + n+1] = tanhf(acc[m][t][3] + c1p[n+1]);
        }
    }
}

// ---- kernel: bilinear logits via HMMA, 1-pass fp16, half2 A-gen -----------
// (R14 winner: 256 threads = 8 warps = 8 m-tiles)
// grid (16 rowblocks, 12 g, KSPL halves)
#define ZSH 40   // half stride for zs slice
#define ZOP 34   // uint (half2) stride for zo pairs
// dyn smem: zs 128*40*2=10240 + zo 128*34*4=17408 + Wst 8*13*32*8=26624 = 54272
__global__ __launch_bounds__(256) void k_blmma() {
    const int g    = blockIdx.y;
    const int r0   = blockIdx.x * 128;
    const int half = blockIdx.z;
    extern __shared__ char shb[];
    __half*   zs_h = (__half*)shb;
    unsigned* zo_p = (unsigned*)(shb + 128*ZSH*2);
    uint2*    Wst  = (uint2*)(shb + 128*ZSH*2 + 128*ZOP*4);
    const int tid = threadIdx.x, lane = tid & 31, wid = tid >> 5;

    for (int idx = tid; idx < 128*8; idx += 256) {
        const int row = idx >> 3, c4 = (idx & 7) * 4;
        float4 a = *(const float4*)&g_zs[(size_t)(r0+row)*D + g*BLKSZ + half*32 + c4];
        *(unsigned*)&zs_h[row*ZSH + c4]     = h2pack(a.x, a.y);
        *(unsigned*)&zs_h[row*ZSH + c4 + 2] = h2pack(a.z, a.w);
    }
    for (int idx = tid; idx < 128*16; idx += 256) {
        const int row = idx >> 4, c4 = (idx & 15) * 4;
        float4 b = *(const float4*)&g_zo[(size_t)(r0+row)*D + g*BLKSZ + c4];
        zo_p[row*ZOP + (idx & 15)*2]     = h2pack(b.x, b.y);
        zo_p[row*ZOP + (idx & 15)*2 + 1] = h2pack(b.z, b.w);
    }

    float acc[13][4] = {};
    const int rl = wid*16 + (lane >> 2);
    const int jpo = lane & 3;
    const uint2* __restrict__ Wh = g_Whi + ((size_t)g*256 + half*128)*13*32;

    for (int sc = 0; sc < 128; sc += 8) {
        __syncthreads();
        for (int idx = tid; idx < 8*13*32; idx += 256)
            Wst[idx] = Wh[(size_t)sc*13*32 + idx];
        __syncthreads();
        #pragma unroll
        for (int sl = 0; sl < 8; sl++) {
            const int s = sc + sl;
            const int i  = s >> 2;
            const int jp = ((s & 3) << 3) + jpo;
            const __half2 z0 = __half2half2(zs_h[rl*ZSH + i]);
            const __half2 z1 = __half2half2(zs_h[(rl+8)*ZSH + i]);
            const unsigned zs0 = reinterpret_cast<const unsigned&>(z0);
            const unsigned zs1 = reinterpret_cast<const unsigned&>(z1);
            unsigned ah[4];
            ah[0] = hmul2u(zs0, zo_p[ rl   *ZOP + jp]);
            ah[1] = hmul2u(zs1, zo_p[(rl+8)*ZOP + jp]);
            ah[2] = hmul2u(zs0, zo_p[ rl   *ZOP + jp + 4]);
            ah[3] = hmul2u(zs1, zo_p[(rl+8)*ZOP + jp + 4]);
            #pragma unroll
            for (int t = 0; t < 13; t++) {
                const uint2 bh = Wst[(sl*13 + t)*32 + lane];
                mma16816(acc[t], ah, bh.x, bh.y);
            }
        }
    }

    float* outp = g_part + ((size_t)(g*KSPL + half) * ROWS + r0) * NL;
    const int r = rl;
    #pragma unroll
    for (int t = 0; t < 13; t++) {
        const int n = t*8 + (lane & 3)*2;
        if (n < NL) {
            outp[(size_t) r   *NL + n] = acc[t][0];
            outp[(size_t)(r+8)*NL + n] = acc[t][2];
        }
        if (n + 1 < NL) {
            outp[(size_t) r   *NL + n+1] = acc[t][1];
            outp[(size_t)(r+8)*NL + n+1] = acc[t][3];
        }
    }
}

// ---- kernel: reduce partials over slices, add bias ------------------------
__global__ void k_reduce(const float* __restrict__ b_bi, float* __restrict__ out) {
    const int idx = blockIdx.x * 256 + threadIdx.x;
    if (idx >= ROWS * NL) return;
    const int n = idx % NL;
    float s = b_bi[n];
    #pragma unroll
    for (int g = 0; g < NSL; g++)
        s += g_part[(size_t)g * (ROWS*NL) + idx];
    out[idx] = s;
}

// ---------------------------------------------------------------------------
extern "C" void kernel_launch(void* const* d_in, const int* in_sizes, int n_in,
                              void* d_out, int out_size) {
    const float* seq    = (const float*)d_in[0];
    const float* att    = (const float*)d_in[1];
    const int*   mpos   = (const int*)d_in[2];
    const int*   hts    = (const int*)d_in[3];
    const float* W_head = (const float*)d_in[4];
    const float* b_head = (const float*)d_in[5];
    const float* W_tail = (const float*)d_in[6];
    const float* b_tail = (const float*)d_in[7];
    const float* W_bi   = (const float*)d_in[8];
    const float* b_bi   = (const float*)d_in[9];
    float* out = (float*)d_out;

    const int blm_smem = 128*ZSH*2 + 128*ZOP*4 + 8*13*32*8;        // 54272
    const int ps_smem  = 16*772*4;                                  // 49408
    const int rs_smem  = 64*72*2 + 1024*8;                          // 17408
    const int eg_smem  = 128*EG_STR*2 + 1536*8;                     // 63488
    const int ex_smem  = 128*72*2 + 1024*8 + 512;                   // 27136
    cudaFuncSetAttribute(k_blmma, cudaFuncAttributeMaxDynamicSharedMemorySize, blm_smem);
    cudaFuncSetAttribute(k_prepS, cudaFuncAttributeMaxDynamicSharedMemorySize, ps_smem);
    cudaFuncSetAttribute(k_rs_mma, cudaFuncAttributeMaxDynamicSharedMemorySize, rs_smem);
    cudaFuncSetAttribute(k_entgemm, cudaFuncAttributeMaxDynamicSharedMemorySize, eg_smem);
    cudaFuncSetAttribute(k_extract2, cudaFuncAttributeMaxDynamicSharedMemorySize, ex_smem);

    k_eatt_eemb<<<B*NE*H + B*NE, 256>>>(att, seq, mpos);
    k_prepS<<<448, 256, ps_smem>>>(W_head, W_tail, seq);
    k_htw_prepW<<<ROWS + 3072 + 252, 256>>>(hts, W_bi, b_head, b_tail);
    dim3 geg(24, 2, 8);
    k_entgemm<<<geg, 256, eg_smem>>>(0);
    dim3 grs(D/64, P/64, B);
    k_rs_mma<<<grs, 256, rs_smem>>>();
    dim3 gex(24, ROWS/128);
    k_extract2<<<gex, 256, ex_smem>>>(hts);
    dim3 glg(ROWS/128, GB, KSPL);
    k_blmma<<<glg, 256, blm_smem>>>();
    k_reduce<<<(ROWS*NL + 255)/256, 256>>>(b_bi, out);
}

// round 17
// speedup vs baseline: 1.1288x; 1.0269x over previous
#include <cuda_runtime.h>
#include <cuda_fp16.h>
#include <math.h>
#include <stdint.h>

#define B 4
#define L 1024
#define D 768
#define H 12
#define NE 42
#define MM 4
#define P 512
#define BLKSZ 64
#define NL 97
#define GB 12          // D / BLKSZ
#define KSPL 2         // K-split of bilinear
#define ROWS (B*P)     // 2048
#define NENT (B*NE)    // 168

// ---------------- scratch (device globals; no allocation allowed) ----------
__device__ __align__(16) __half g_ehi[NENT*D];
__device__ __align__(16) float g_eatt[B*NE*H*L];
__device__ __align__(16) __half g_hthi[(size_t)ROWS*L];
__device__ __align__(16) __half g_rshi[(size_t)ROWS*D];
__device__ __align__(16) float g_cent[2*NENT*D];      // bias-preinit; entgemm atomically adds
__device__ __align__(16) float g_zs[(size_t)ROWS*D];
__device__ __align__(16) float g_zo[(size_t)ROWS*D];
// fragment-ready W_bi (hi fp16): [g][kstep s:256][ntile t:13][lane:32]
__device__ __align__(16) uint2 g_Whi[(size_t)GB*256*13*32];
// fragment-ready extractor weights (hi only): [which:2][kstep:96][ntile:96][lane:32]
__device__ __align__(16) uint2 g_WxFhi[(size_t)2*96*96*32];
// fragment-ready seq (hi only): [b:4][kstep:64][ntile:96][lane:32]
__device__ __align__(16) uint2 g_seqFhi[(size_t)4*64*96*32];

// ---- half helpers ---------------------------------------------------------
__device__ __forceinline__ unsigned h2pack(float a, float b) {
    __half2 h = __float22half2_rn(make_float2(a, b));
    return reinterpret_cast<unsigned&>(h);
}
__device__ __forceinline__ unsigned hmul2u(unsigned a, unsigned b) {
    __half2 r = __hmul2(reinterpret_cast<__half2&>(a), reinterpret_cast<__half2&>(b));
    return reinterpret_cast<unsigned&>(r);
}

// ---- mma.sync m16n8k16 fp16 -> fp32 ---------------------------------------
__device__ __forceinline__ void mma16816(float* d, const unsigned* a, unsigned b0, unsigned b1) {
    asm volatile(
        "mma.sync.aligned.m16n8k16.row.col.f32.f16.f16.f32 "
        "{%0,%1,%2,%3}, {%4,%5,%6,%7}, {%8,%9}, {%0,%1,%2,%3};"
        : "+f"(d[0]), "+f"(d[1]), "+f"(d[2]), "+f"(d[3])
        : "r"(a[0]), "r"(a[1]), "r"(a[2]), "r"(a[3]), "r"(b0), "r"(b1));
}

// ---- fused kernel: entity attentions (bids 0..2015) + embeddings (2016..) -
__global__ void k_eatt_eemb(const float* __restrict__ att,
                            const float* __restrict__ seq,
                            const int* __restrict__ mpos) {
    __shared__ int pos[MM];
    const int tid = threadIdx.x;
    if ((int)blockIdx.x < B*NE*H) {
        const int idx = blockIdx.x;
        const int h  = idx % H;
        const int be = idx / H;
        const int b  = be / NE;
        if (tid < MM) pos[tid] = mpos[be*MM + tid] + 1;
        __syncthreads();
        const float* ab = att + (size_t)(b*H + h) * L * L;
        const float4* a0 = (const float4*)(ab + (size_t)pos[0]*L);
        const float4* a1 = (const float4*)(ab + (size_t)pos[1]*L);
        const float4* a2 = (const float4*)(ab + (size_t)pos[2]*L);
        const float4* a3 = (const float4*)(ab + (size_t)pos[3]*L);
        float4* o4 = (float4*)(g_eatt + ((size_t)be*H + h) * L);
        const float4 v0 = a0[tid], v1 = a1[tid], v2 = a2[tid], v3 = a3[tid];
        float4 s;
        s.x = 0.25f*(v0.x + v1.x + v2.x + v3.x);
        s.y = 0.25f*(v0.y + v1.y + v2.y + v3.y);
        s.z = 0.25f*(v0.z + v1.z + v2.z + v3.z);
        s.w = 0.25f*(v0.w + v1.w + v2.w + v3.w);
        o4[tid] = s;
    } else {
        const int be = blockIdx.x - B*NE*H;
        const int b = be / NE;
        if (tid < MM) pos[tid] = mpos[be*MM + tid] + 1;
        __syncthreads();
        if (tid < 192) {
            const float* sb = seq + (size_t)b * L * D;
            const float4 v0 = *(const float4*)(sb + (size_t)pos[0]*D + tid*4);
            const float4 v1 = *(const float4*)(sb + (size_t)pos[1]*D + tid*4);
            const float4 v2 = *(const float4*)(sb + (size_t)pos[2]*D + tid*4);
            const float4 v3 = *(const float4*)(sb + (size_t)pos[3]*D + tid*4);
            float r[4];
            #pragma unroll
            for (int j = 0; j < 4; j++) {
                const float e0 = (&v0.x)[j], e1 = (&v1.x)[j];
                const float e2 = (&v2.x)[j], e3 = (&v3.x)[j];
                float mx = fmaxf(fmaxf(e0, e1), fmaxf(e2, e3));
                float s = expf(e0-mx) + expf(e1-mx) + expf(e2-mx) + expf(e3-mx);
                r[j] = mx + logf(s);
            }
            *(unsigned*)&g_ehi[(size_t)be*D + tid*4]     = h2pack(r[0], r[1]);
            *(unsigned*)&g_ehi[(size_t)be*D + tid*4 + 2] = h2pack(r[2], r[3]);
        }
    }
}

// ---- fused: htw (0..2047) + W_bi prep (+3072) + cent init (+252) + out init (+194)
__global__ void k_htw_prepW(const int* __restrict__ hts, const float* __restrict__ Wbi,
                            const float* __restrict__ bh_, const float* __restrict__ bt_,
                            const float* __restrict__ b_bi, float* __restrict__ out) {
    __shared__ float sbuf[16*97];               // prepW slab; htw uses first 256 as red
    const int tid = threadIdx.x;
    if ((int)blockIdx.x < ROWS) {
        const int bp = blockIdx.x;
        const int b  = bp / P;
        const int hi = hts[bp*2 + 0];
        const int ti = hts[bp*2 + 1];
        const float4* eh4 = (const float4*)(g_eatt + (size_t)(b*NE + hi) * H * L);
        const float4* et4 = (const float4*)(g_eatt + (size_t)(b*NE + ti) * H * L);
        float ax = 0.f, ay = 0.f, az = 0.f, aw = 0.f;
        #pragma unroll
        for (int hh = 0; hh < H; hh++) {
            const float4 a = eh4[hh*256 + tid];
            const float4 c = et4[hh*256 + tid];
            ax += a.x*c.x; ay += a.y*c.y; az += a.z*c.z; aw += a.w*c.w;
        }
        float lsum = ax + ay + az + aw;
        sbuf[tid] = lsum;
        __syncthreads();
        for (int s = 128; s > 0; s >>= 1) {
            if (tid < s) sbuf[tid] += sbuf[tid + s];
            __syncthreads();
        }
        const float total = sbuf[0];
        const float scale = 1.f / ((float)H * (total / (float)H + 1e-5f));
        *(unsigned*)&g_hthi[(size_t)bp*L + tid*4]     = h2pack(ax*scale, ay*scale);
        *(unsigned*)&g_hthi[(size_t)bp*L + tid*4 + 2] = h2pack(az*scale, aw*scale);
    } else if ((int)blockIdx.x < ROWS + 3072) {
        const int bid = blockIdx.x - ROWS;
        const int s = bid & 255, g = bid >> 8;
        const float4* src = (const float4*)(Wbi + (size_t)(g*4096 + s*16)*NL);
        for (int idx = tid; idx < 388; idx += 256)
            ((float4*)sbuf)[idx] = src[idx];
        __syncthreads();
        for (int o = tid; o < 13*32; o += 256) {
            const int t = o >> 5, lane = o & 31;
            const int n = t*8 + (lane >> 2), kk = (lane & 3)*2;
            float w00 = 0.f, w01 = 0.f, w08 = 0.f, w09 = 0.f;
            if (n < NL) {
                w00 = sbuf[(kk  )*97 + n]; w01 = sbuf[(kk+1)*97 + n];
                w08 = sbuf[(kk+8)*97 + n]; w09 = sbuf[(kk+9)*97 + n];
            }
            g_Whi[((size_t)(g*256 + s)*13 + t)*32 + lane] =
                make_uint2(h2pack(w00, w01), h2pack(w08, w09));
        }
    } else if ((int)blockIdx.x < ROWS + 3072 + 252) {
        const int base = ((int)blockIdx.x - (ROWS + 3072)) * 1024 + tid * 4;
        const int which = base / (NENT*D);
        const int n = base % D;
        const float* bias = which ? bt_ : bh_;
        float4 v = *(const float4*)&bias[n];
        *(float4*)&g_cent[base] = v;
    } else {
        // out init: out[row][n] = b_bi[n]; 194 blocks x 1024 elems = ROWS*NL exactly
        const int base = ((int)blockIdx.x - (ROWS + 3072 + 252)) * 1024 + tid * 4;
        #pragma unroll
        for (int j = 0; j < 4; j++)
            out[base + j] = b_bi[(base + j) % NL];
    }
}

// ---- kernel: big slabs (W_head/W_tail/seq) -> fragment-ready fp16 ---------
// bids [0,192): extractor weights; [192,448): seq. dyn smem 49408 B.
__global__ void k_prepS(const float* __restrict__ Wh, const float* __restrict__ Wt,
                        const float* __restrict__ seq) {
    extern __shared__ float smf[];
    const int tid = threadIdx.x;               // 256
    const int bid = blockIdx.x;
    const float* src;
    uint2* dhi;
    if (bid < 192) {
        const int which = bid / 96, ks = bid % 96;
        src = (which ? Wt : Wh) + (size_t)ks*16*768;
        dhi = g_WxFhi + ((size_t)which*96 + ks)*96*32;
    } else {
        const int r = bid - 192;
        const int b = r / 64, ks = r % 64;
        src = seq + (size_t)b*L*D + (size_t)ks*16*768;
        dhi = g_seqFhi + ((size_t)b*64 + ks)*96*32;
    }
    for (int idx = tid; idx < 16*192; idx += 256) {
        const int kr = idx / 192, n4 = idx - kr*192;
        const float4 v = *(const float4*)(src + (size_t)kr*768 + n4*4);
        *(float4*)&smf[kr*772 + n4*4] = v;
    }
    __syncthreads();
    for (int o = tid; o < 96*32; o += 256) {
        const int nt = o >> 5, lane = o & 31;
        const int n = nt*8 + (lane >> 2), k0 = (lane & 3)*2;
        unsigned h0 = h2pack(smf[(k0  )*772 + n], smf[(k0+1)*772 + n]);
        unsigned h1 = h2pack(smf[(k0+8)*772 + n], smf[(k0+9)*772 + n]);
        dhi[(size_t)nt*32 + lane] = make_uint2(h0, h1);
    }
}

// ---- fused GEMM kernel: rs (bids 0..383) + entgemm split-K (384..767) -----
// dyn smem: 17408 B (rs: Ah 64*72*2 + Bhs 1024*8; ent: Bhs 1536*8 = 12288)
__global__ __launch_bounds__(256) void k_gemms() {
    extern __shared__ char dsm[];
    const int tid = threadIdx.x, lane = tid & 31, wid = tid >> 5;
    if ((int)blockIdx.x < 384) {
        // ---------------- rs = htw @ seq (1-pass fp16) ---------------------
        const int ntb = blockIdx.x % 12;
        const int py  = (blockIdx.x / 12) & 7;
        const int b   = blockIdx.x / 96;
        const int p0  = py * 64;
        __half* Ah = (__half*)dsm;
        uint2*  Bhs = (uint2*)(dsm + 64*72*2);
        const int wm = wid & 1, wn = wid >> 1;
        const size_t rowbase = (size_t)(b*P + p0);
        float acc[2][2][4] = {};
        const int rb = wm*32 + (lane >> 2);
        for (int c0 = 0; c0 < L; c0 += 64) {
            __syncthreads();
            for (int idx = tid; idx < 1024; idx += 256) {
                const int row = idx >> 4, c4 = (idx & 15)*4;
                const size_t o = (rowbase + row)*L + c0 + c4;
                *(uint2*)&Ah[row*72 + c4] = *(const uint2*)&g_hthi[o];
            }
            for (int idx = tid; idx < 1024; idx += 256) {
                const int kl = idx >> 8, rest = idx & 255;
                const int nt = ntb*8 + (rest >> 5), l2 = rest & 31;
                const size_t bi = (((size_t)b*64 + (c0 >> 4) + kl)*96 + nt)*32 + l2;
                Bhs[idx] = g_seqFhi[bi];
            }
            __syncthreads();
            #pragma unroll
            for (int kk = 0; kk < 4; kk++) {
                const int kloc = kk*16 + (lane & 3)*2;
                unsigned ah[2][4];
                #pragma unroll
                for (int m = 0; m < 2; m++) {
                    const int r = rb + m*16;
                    ah[m][0] = *(const unsigned*)&Ah[ r   *72 + kloc];
                    ah[m][1] = *(const unsigned*)&Ah[(r+8)*72 + kloc];
                    ah[m][2] = *(const unsigned*)&Ah[ r   *72 + kloc + 8];
                    ah[m][3] = *(const unsigned*)&Ah[(r+8)*72 + kloc + 8];
                }
                #pragma unroll
                for (int t = 0; t < 2; t++) {
                    const int bi = (kk*8 + wn*2 + t)*32 + lane;
                    const uint2 bh = Bhs[bi];
                    #pragma unroll
                    for (int m = 0; m < 2; m++)
                        mma16816(acc[m][t], ah[m], bh.x, bh.y);
                }
            }
        }
        #pragma unroll
        for (int m = 0; m < 2; m++) {
            const size_t r = rowbase + wm*32 + m*16 + (lane >> 2);
            #pragma unroll
            for (int t = 0; t < 2; t++) {
                const int n = ntb*64 + wn*16 + t*8 + (lane & 3)*2;
                *(unsigned*)&g_rshi[ r   *D + n] = h2pack(acc[m][t][0], acc[m][t][1]);
                *(unsigned*)&g_rshi[(r+8)*D + n] = h2pack(acc[m][t][2], acc[m][t][3]);
            }
        }
    } else {
        // ---------- entgemm split-K, A fragments direct from L2 ------------
        const int e = blockIdx.x - 384;
        const int ntb = e % 24;
        const int rby = (e / 24) & 1;
        const int wkz = e / 48;                 // which*4 + ks
        const int which = wkz >> 2, ks = wkz & 3;
        const int r0 = rby * 128;
        const int c0 = ks * 192;
        uint2* Bhs = (uint2*)dsm;
        const int wm = wid & 3, wn = wid >> 2;
        const uint2* __restrict__ WFh = g_WxFhi + (size_t)which*96*96*32;
        float acc[2][2][4] = {};
        const int rb = wm*32 + (lane >> 2);
        for (int idx = tid; idx < 1536; idx += 256) {
            const int kl = idx >> 7, rest = idx & 127;
            const int nt = ntb*4 + (rest >> 5), l2 = rest & 31;
            Bhs[idx] = WFh[((size_t)((c0 >> 4) + kl)*96 + nt)*32 + l2];
        }
        __syncthreads();
        #pragma unroll
        for (int kk = 0; kk < 12; kk++) {
            const int kloc = kk*16 + (lane & 3)*2;
            unsigned ah[2][4];
            #pragma unroll
            for (int m = 0; m < 2; m++) {
                int r = rb + m*16;
                int be0 = r0 + r;     if (be0 >= NENT) be0 = 0;
                int be1 = r0 + r + 8; if (be1 >= NENT) be1 = 0;
                ah[m][0] = *(const unsigned*)&g_ehi[(size_t)be0*D + c0 + kloc];
                ah[m][1] = *(const unsigned*)&g_ehi[(size_t)be1*D + c0 + kloc];
                ah[m][2] = *(const unsigned*)&g_ehi[(size_t)be0*D + c0 + kloc + 8];
                ah[m][3] = *(const unsigned*)&g_ehi[(size_t)be1*D + c0 + kloc + 8];
            }
            #pragma unroll
            for (int t = 0; t < 2; t++) {
                const int bi = (kk*4 + wn*2 + t)*32 + lane;
                const uint2 bh = Bhs[bi];
                #pragma unroll
                for (int m = 0; m < 2; m++)
                    mma16816(acc[m][t], ah[m], bh.x, bh.y);
            }
        }
        float* cent = g_cent + (size_t)which*NENT*D;
        #pragma unroll
        for (int m = 0; m < 2; m++) {
            const int r = r0 + wm*32 + m*16 + (lane >> 2);
            #pragma unroll
            for (int t = 0; t < 2; t++) {
                const int n = ntb*32 + wn*16 + t*8 + (lane & 3)*2;
                if (r < NENT) {
                    atomicAdd(&cent[(size_t)r*D + n  ], acc[m][t][0]);
                    atomicAdd(&cent[(size_t)r*D + n+1], acc[m][t][1]);
                }
                if (r + 8 < NENT) {
                    atomicAdd(&cent[(size_t)(r+8)*D + n  ], acc[m][t][2]);
                    atomicAdd(&cent[(size_t)(r+8)*D + n+1], acc[m][t][3]);
                }
            }
        }
    }
}

// ---- kernel: pair extractor: z = tanh(rs @ W2 + cent[ent(p)]) -------------
// 1-pass fp16; grid.x = 24 (which*12+nb), grid.y = 16; 256 threads
__global__ __launch_bounds__(256) void k_extract2(const int* __restrict__ hts) {
    const int which = blockIdx.x / 12;
    const int nb    = blockIdx.x % 12;
    const int r0 = blockIdx.y * 128;
    extern __shared__ char dsm[];
    __half* Ah = (__half*)dsm;
    uint2*  Bhs = (uint2*)(dsm + 128*72*2);
    int*    eoff = (int*)(Bhs + 1024);
    const int tid = threadIdx.x, lane = tid & 31, wid = tid >> 5;
    const int wm = wid & 3, wn = wid >> 2;
    if (tid < 128) {
        const int row = r0 + tid;
        eoff[tid] = ((row / P)*NE + hts[row*2 + which]) * D;
    }
    const uint2* __restrict__ WFh = g_WxFhi + (size_t)which*96*96*32;
    float acc[2][4][4] = {};
    const int rb = wm*32 + (lane >> 2);
    for (int c0 = 0; c0 < D; c0 += 64) {
        __syncthreads();
        for (int idx = tid; idx < 2048; idx += 256) {
            const int row = idx >> 4, c4 = (idx & 15)*4;
            const size_t o = (size_t)(r0 + row)*D + c0 + c4;
            *(uint2*)&Ah[row*72 + c4] = *(const uint2*)&g_rshi[o];
        }
        for (int idx = tid; idx < 1024; idx += 256) {
            const int kl = idx >> 8, rest = idx & 255;
            const int nt = nb*8 + (rest >> 5), l2 = rest & 31;
            Bhs[idx] = WFh[((size_t)(48 + (c0 >> 4) + kl)*96 + nt)*32 + l2];
        }
        __syncthreads();
        #pragma unroll
        for (int kk = 0; kk < 4; kk++) {
            const int kloc = kk*16 + (lane & 3)*2;
            unsigned ah[2][4];
            #pragma unroll
            for (int m = 0; m < 2; m++) {
                const int r = rb + m*16;
                ah[m][0] = *(const unsigned*)&Ah[ r   *72 + kloc];
                ah[m][1] = *(const unsigned*)&Ah[(r+8)*72 + kloc];
                ah[m][2] = *(const unsigned*)&Ah[ r   *72 + kloc + 8];
                ah[m][3] = *(const unsigned*)&Ah[(r+8)*72 + kloc + 8];
            }
            #pragma unroll
            for (int t = 0; t < 4; t++) {
                const int bi = (kk*8 + wn*4 + t)*32 + lane;
                const uint2 bh = Bhs[bi];
                #pragma unroll
                for (int m = 0; m < 2; m++)
                    mma16816(acc[m][t], ah[m], bh.x, bh.y);
            }
        }
    }
    float* outb = which ? g_zo : g_zs;
    const float* cent = g_cent + (size_t)which*NENT*D;
    #pragma unroll
    for (int m = 0; m < 2; m++) {
        const int lr = wm*32 + m*16 + (lane >> 2);
        const int r = r0 + lr;
        #pragma unroll
        for (int t = 0; t < 4; t++) {
            const int n = nb*64 + wn*32 + t*8 + (lane & 3)*2;
            const float* c0p = cent + eoff[lr];
            const float* c1p = cent + eoff[lr + 8];
            outb[(size_t) r   *D + n  ] = tanhf(acc[m][t][0] + c0p[n]);
            outb[(size_t) r   *D + n+1] = tanhf(acc[m][t][1] + c0p[n+1]);
            outb[(size_t)(r+8)*D + n  ] = tanhf(acc[m][t][2] + c1p[n]);
            outb[(size_t)(r+8)*D + n+1] = tanhf(acc[m][t][3] + c1p[n+1]);
        }
    }
}

// ---- kernel: bilinear logits via HMMA, atomic accumulate into out ---------
// (256 threads = 8 warps = 8 m-tiles); grid (16 rowblocks, 12 g, KSPL halves)
#define ZSH 40   // half stride for zs slice
#define ZOP 34   // uint (half2) stride for zo pairs
// dyn smem: zs 128*40*2=10240 + zo 128*34*4=17408 + Wst 8*13*32*8=26624 = 54272
__global__ __launch_bounds__(256) void k_blmma(float* __restrict__ out) {
    const int g    = blockIdx.y;
    const int r0   = blockIdx.x * 128;
    const int half = blockIdx.z;
    extern __shared__ char shb[];
    __half*   zs_h = (__half*)shb;
    unsigned* zo_p = (unsigned*)(shb + 128*ZSH*2);
    uint2*    Wst  = (uint2*)(shb + 128*ZSH*2 + 128*ZOP*4);
    const int tid = threadIdx.x, lane = tid & 31, wid = tid >> 5;

    for (int idx = tid; idx < 128*8; idx += 256) {
        const int row = idx >> 3, c4 = (idx & 7) * 4;
        float4 a = *(const float4*)&g_zs[(size_t)(r0+row)*D + g*BLKSZ + half*32 + c4];
        *(unsigned*)&zs_h[row*ZSH + c4]     = h2pack(a.x, a.y);
        *(unsigned*)&zs_h[row*ZSH + c4 + 2] = h2pack(a.z, a.w);
    }
    for (int idx = tid; idx < 128*16; idx += 256) {
        const int row = idx >> 4, c4 = (idx & 15) * 4;
        float4 b = *(const float4*)&g_zo[(size_t)(r0+row)*D + g*BLKSZ + c4];
        zo_p[row*ZOP + (idx & 15)*2]     = h2pack(b.x, b.y);
        zo_p[row*ZOP + (idx & 15)*2 + 1] = h2pack(b.z, b.w);
    }

    float acc[13][4] = {};
    const int rl = wid*16 + (lane >> 2);
    const int jpo = lane & 3;
    const uint2* __restrict__ Wh = g_Whi + ((size_t)g*256 + half*128)*13*32;

    for (int sc = 0; sc < 128; sc += 8) {
        __syncthreads();
        for (int idx = tid; idx < 8*13*32; idx += 256)
            Wst[idx] = Wh[(size_t)sc*13*32 + idx];
        __syncthreads();
        #pragma unroll
        for (int sl = 0; sl < 8; sl++) {
            const int s = sc + sl;
            const int i  = s >> 2;
            const int jp = ((s & 3) << 3) + jpo;
            const __half2 z0 = __half2half2(zs_h[rl*ZSH + i]);
            const __half2 z1 = __half2half2(zs_h[(rl+8)*ZSH + i]);
            const unsigned zs0 = reinterpret_cast<const unsigned&>(z0);
            const unsigned zs1 = reinterpret_cast<const unsigned&>(z1);
            unsigned ah[4];
            ah[0] = hmul2u(zs0, zo_p[ rl   *ZOP + jp]);
            ah[1] = hmul2u(zs1, zo_p[(rl+8)*ZOP + jp]);
            ah[2] = hmul2u(zs0, zo_p[ rl   *ZOP + jp + 4]);
            ah[3] = hmul2u(zs1, zo_p[(rl+8)*ZOP + jp + 4]);
            #pragma unroll
            for (int t = 0; t < 13; t++) {
                const uint2 bh = Wst[(sl*13 + t)*32 + lane];
                mma16816(acc[t], ah, bh.x, bh.y);
            }
        }
    }

    const size_t row0 = (size_t)(r0 + rl);
    #pragma unroll
    for (int t = 0; t < 13; t++) {
        const int n = t*8 + (lane & 3)*2;
        if (n < NL) {
            atomicAdd(&out[ row0     *NL + n], acc[t][0]);
            atomicAdd(&out[(row0 + 8)*NL + n], acc[t][2]);
        }
        if (n + 1 < NL) {
            atomicAdd(&out[ row0     *NL + n+1], acc[t][1]);
            atomicAdd(&out[(row0 + 8)*NL + n+1], acc[t][3]);
        }
    }
}

// ---------------------------------------------------------------------------
extern "C" void kernel_launch(void* const* d_in, const int* in_sizes, int n_in,
                              void* d_out, int out_size) {
    const float* seq    = (const float*)d_in[0];
    const float* att    = (const float*)d_in[1];
    const int*   mpos   = (const int*)d_in[2];
    const int*   hts    = (const int*)d_in[3];
    const float* W_head = (const float*)d_in[4];
    const float* b_head = (const float*)d_in[5];
    const float* W_tail = (const float*)d_in[6];
    const float* b_tail = (const float*)d_in[7];
    const float* W_bi   = (const float*)d_in[8];
    const float* b_bi   = (const float*)d_in[9];
    float* out = (float*)d_out;

    const int blm_smem = 128*ZSH*2 + 128*ZOP*4 + 8*13*32*8;        // 54272
    const int ps_smem  = 16*772*4;                                  // 49408
    const int gm_smem  = 64*72*2 + 1024*8;                          // 17408
    const int ex_smem  = 128*72*2 + 1024*8 + 512;                   // 27136
    cudaFuncSetAttribute(k_blmma, cudaFuncAttributeMaxDynamicSharedMemorySize, blm_smem);
    cudaFuncSetAttribute(k_prepS, cudaFuncAttributeMaxDynamicSharedMemorySize, ps_smem);
    cudaFuncSetAttribute(k_gemms, cudaFuncAttributeMaxDynamicSharedMemorySize, gm_smem);
    cudaFuncSetAttribute(k_extract2, cudaFuncAttributeMaxDynamicSharedMemorySize, ex_smem);

    k_eatt_eemb<<<B*NE*H + B*NE, 256>>>(att, seq, mpos);
    k_prepS<<<448, 256, ps_smem>>>(W_head, W_tail, seq);
    k_htw_prepW<<<ROWS + 3072 + 252 + 194, 256>>>(hts, W_bi, b_head, b_tail, b_bi, out);
    k_gemms<<<768, 256, gm_smem>>>();
    dim3 gex(24, ROWS/128);
    k_extract2<<<gex, 256, ex_smem>>>(hts);
    dim3 glg(ROWS/128, GB, KSPL);
    k_blmma<<<glg, 256, blm_smem>>>(out);
}